// round 15
// baseline (speedup 1.0000x reference)
#include <cuda_runtime.h>
#include <cuda_bf16.h>
#include <cstdint>
#include <math.h>

#define DIM   512
#define CDIM  128
#define CSIZE 8192
#define MMAX  16384
#define EPSV  1e-6f
#define CAP   192

// ---- int8 dist kernel tiling: KCB=64 bytes/stage, 3 buffers, single sync ----
#define MT 128
#define NT 128
#define KCB 64
#define NSTG (DIM / KCB)          // 8
#define ROWB 80                   // 64 s8 + 16B pad (conflict-free ldmatrix)
#define BUFSZ (128 * ROWB)        // 10240
#define OFF_B BUFSZ
#define SM_STAGE (2 * BUFSZ)      // 20480
#define SM_BUF0 2048              // cc/sc/l1c tiles
#define SM_TOTAL (SM_BUF0 + 3 * SM_STAGE)   // 63488

// ---- bf16x3 transform-GEMM tiling (round-14 proven) ----
#define ROWB2 80
#define BUFSZ2 (128 * ROWB2)
#define G2_OFF_ALO (1 * BUFSZ2)
#define G2_OFF_BHI (2 * BUFSZ2)
#define G2_OFF_BLO (3 * BUFSZ2)
#define G2_STAGE (4 * BUFSZ2)
#define G2_TOTAL (2 * G2_STAGE)
#define KC2 32
#define NSTG2 (DIM / KC2)         // 16 (gemm2)
#define NSTG1 (CDIM / KC2)        // 4  (gemm1)

// ---------------- device scratch ----------------
__device__ float g_h[CSIZE * DIM];
__device__ float g_icb[CSIZE * DIM];
__device__ float g_cc[CSIZE];
__device__ float g_ccpart[8 * CSIZE];
__device__ float g_xx[MMAX];
__device__ float g_l1x[MMAX];
__device__ float g_sx[MMAX];
__device__ float g_l1c[CSIZE];
__device__ float g_sc[CSIZE];
__device__ float g_rowloss[MMAX];
__device__ signed char g_qx[MMAX * DIM];
__device__ signed char g_qc[CSIZE * DIM];
__device__ __nv_bfloat16 g_shi[CSIZE * DIM];     // selu(h) hi
__device__ __nv_bfloat16 g_slo[CSIZE * DIM];     // selu(h) lo
__device__ __nv_bfloat16 g_cbhi[CSIZE * CDIM];
__device__ __nv_bfloat16 g_cblo[CSIZE * CDIM];
__device__ __nv_bfloat16 g_w1thi[DIM * CDIM];
__device__ __nv_bfloat16 g_w1tlo[DIM * CDIM];
__device__ __nv_bfloat16 g_w2thi[DIM * DIM];
__device__ __nv_bfloat16 g_w2tlo[DIM * DIM];
__device__ unsigned int g_rowmin[MMAX];
__device__ unsigned int g_ccount[MMAX];
__device__ int g_cand[MMAX * CAP];

// ---------------- helpers ----------------
__device__ __forceinline__ uint32_t smem_u32(const void* p) {
    uint32_t a;
    asm("{ .reg .u64 t; cvta.to.shared.u64 t, %1; cvt.u32.u64 %0, t; }"
        : "=r"(a) : "l"(p));
    return a;
}

#define CP_ASYNC16(dst, src) \
    asm volatile("cp.async.cg.shared.global [%0], [%1], 16;" :: "r"(dst), "l"(src))
#define CP_COMMIT() asm volatile("cp.async.commit_group;" ::: "memory")
#define CP_WAIT1() asm volatile("cp.async.wait_group 1;" ::: "memory")
#define CP_WAIT0() asm volatile("cp.async.wait_group 0;" ::: "memory")

__device__ __forceinline__ void ldm_x4(uint32_t* r, uint32_t addr) {
    asm volatile("ldmatrix.sync.aligned.m8n8.x4.shared.b16 {%0,%1,%2,%3}, [%4];"
                 : "=r"(r[0]), "=r"(r[1]), "=r"(r[2]), "=r"(r[3]) : "r"(addr));
}
__device__ __forceinline__ void ldm_x2(uint32_t* r, uint32_t addr) {
    asm volatile("ldmatrix.sync.aligned.m8n8.x2.shared.b16 {%0,%1}, [%2];"
                 : "=r"(r[0]), "=r"(r[1]) : "r"(addr));
}
__device__ __forceinline__ void mma_bf16(float* c, const uint32_t* a, const uint32_t* b) {
    asm volatile(
        "mma.sync.aligned.m16n8k16.row.col.f32.bf16.bf16.f32 "
        "{%0,%1,%2,%3}, {%4,%5,%6,%7}, {%8,%9}, {%0,%1,%2,%3};"
        : "+f"(c[0]), "+f"(c[1]), "+f"(c[2]), "+f"(c[3])
        : "r"(a[0]), "r"(a[1]), "r"(a[2]), "r"(a[3]), "r"(b[0]), "r"(b[1]));
}
__device__ __forceinline__ void mma_s8(int* c, const uint32_t* a, const uint32_t* b) {
    asm volatile(
        "mma.sync.aligned.m16n8k32.row.col.s32.s8.s8.s32 "
        "{%0,%1,%2,%3}, {%4,%5,%6,%7}, {%8,%9}, {%0,%1,%2,%3};"
        : "+r"(c[0]), "+r"(c[1]), "+r"(c[2]), "+r"(c[3])
        : "r"(a[0]), "r"(a[1]), "r"(a[2]), "r"(a[3]), "r"(b[0]), "r"(b[1]));
}

__device__ __forceinline__ unsigned int ord_enc(float f) {
    unsigned int u = __float_as_uint(f);
    return (u & 0x80000000u) ? ~u : (u | 0x80000000u);
}
__device__ __forceinline__ float ord_dec(unsigned int e) {
    unsigned int u = (e & 0x80000000u) ? (e & 0x7fffffffu) : ~e;
    return __uint_as_float(u);
}

__device__ __forceinline__ float selu_f(float z) {
    const float a = 1.6732632423543772f;
    const float s = 1.0507009873554805f;
    return s * (z > 0.f ? z : a * expm1f(z));
}

__device__ __forceinline__ signed char q8(float v, float inv) {
    int qi = __float2int_rn(v * inv);
    qi = qi > 127 ? 127 : (qi < -127 ? -127 : qi);
    return (signed char)qi;
}

// ---------------- prep_x: xx/l1/sx + int8 quantize + init state ------------
__global__ void prep_x_k(const float* __restrict__ X) {
    int m = blockIdx.x;
    int tid = threadIdx.x;     // 128
    float4 v = *(const float4*)(X + (size_t)m * DIM + tid * 4);

    float ss = v.x * v.x + v.y * v.y + v.z * v.z + v.w * v.w;
    float l1 = fabsf(v.x) + fabsf(v.y) + fabsf(v.z) + fabsf(v.w);
    float am = fmaxf(fmaxf(fabsf(v.x), fabsf(v.y)), fmaxf(fabsf(v.z), fabsf(v.w)));

    float s0 = ss, s1 = l1, s2 = am;
    for (int o = 16; o > 0; o >>= 1) {
        s0 += __shfl_down_sync(0xffffffffu, s0, o);
        s1 += __shfl_down_sync(0xffffffffu, s1, o);
        s2 = fmaxf(s2, __shfl_down_sync(0xffffffffu, s2, o));
    }
    __shared__ float sb[12];
    __shared__ float s_inv;
    int w = tid >> 5;
    if ((tid & 31) == 0) { sb[w] = s0; sb[4 + w] = s1; sb[8 + w] = s2; }
    __syncthreads();
    if (tid == 0) {
        float xx = sb[0] + sb[1] + sb[2] + sb[3];
        float l1t = sb[4] + sb[5] + sb[6] + sb[7];
        float amx = fmaxf(fmaxf(sb[8], sb[9]), fmaxf(sb[10], sb[11]));
        float sx = fmaxf(amx, 1e-20f) / 127.f;
        g_xx[m] = xx;
        g_l1x[m] = l1t;
        g_sx[m] = sx;
        s_inv = 1.f / sx;
        g_rowmin[m] = 0xFFFFFFFFu;
        g_ccount[m] = 0u;
    }
    __syncthreads();
    float inv = s_inv;
    char4 q;
    q.x = q8(v.x, inv); q.y = q8(v.y, inv);
    q.z = q8(v.z, inv); q.w = q8(v.w, inv);
    *(char4*)(g_qx + (size_t)m * DIM + tid * 4) = q;
}

// ---------------- cprep: icb row -> int8 + sc + l1c ----------------
__global__ void cprep_k() {
    int m = blockIdx.x;
    int tid = threadIdx.x;     // 128
    float4 v = *(const float4*)(g_icb + (size_t)m * DIM + tid * 4);

    float l1 = fabsf(v.x) + fabsf(v.y) + fabsf(v.z) + fabsf(v.w);
    float am = fmaxf(fmaxf(fabsf(v.x), fabsf(v.y)), fmaxf(fabsf(v.z), fabsf(v.w)));

    float s1 = l1, s2 = am;
    for (int o = 16; o > 0; o >>= 1) {
        s1 += __shfl_down_sync(0xffffffffu, s1, o);
        s2 = fmaxf(s2, __shfl_down_sync(0xffffffffu, s2, o));
    }
    __shared__ float sb[8];
    __shared__ float s_inv;
    int w = tid >> 5;
    if ((tid & 31) == 0) { sb[w] = s1; sb[4 + w] = s2; }
    __syncthreads();
    if (tid == 0) {
        float l1t = sb[0] + sb[1] + sb[2] + sb[3];
        float amx = fmaxf(fmaxf(sb[4], sb[5]), fmaxf(sb[6], sb[7]));
        float sc = fmaxf(amx, 1e-20f) / 127.f;
        g_l1c[m] = l1t;
        g_sc[m] = sc;
        s_inv = 1.f / sc;
    }
    __syncthreads();
    float inv = s_inv;
    char4 q;
    q.x = q8(v.x, inv); q.y = q8(v.y, inv);
    q.z = q8(v.z, inv); q.w = q8(v.w, inv);
    *(char4*)(g_qc + (size_t)m * DIM + tid * 4) = q;
}

// ---------------- cb bf16 hi/lo split ----------------
__global__ void cbprep_k(const float* __restrict__ cb) {
    int i = (blockIdx.x * 256 + threadIdx.x) * 4;
    float4 v = *(const float4*)(cb + i);
    float vv[4] = {v.x, v.y, v.z, v.w};
#pragma unroll
    for (int q = 0; q < 4; q++) {
        __nv_bfloat16 hi = __float2bfloat16(vv[q]);
        g_cbhi[i + q] = hi;
        g_cblo[i + q] = __float2bfloat16(vv[q] - __bfloat162float(hi));
    }
}

// ---------------- W transpose + bf16 split ----------------
__global__ void wtprep_k(const float* __restrict__ W, __nv_bfloat16* __restrict__ thi,
                         __nv_bfloat16* __restrict__ tlo, int K, int N) {
    __shared__ float t[32][33];
    int bx = blockIdx.x * 32, by = blockIdx.y * 32;
    int tx = threadIdx.x, ty = threadIdx.y;           // 32x8
#pragma unroll
    for (int i = 0; i < 4; i++)
        t[ty + i * 8][tx] = W[(size_t)(by + ty + i * 8) * N + bx + tx];
    __syncthreads();
#pragma unroll
    for (int i = 0; i < 4; i++) {
        int n = bx + ty + i * 8, k = by + tx;
        float v = t[tx][ty + i * 8];
        __nv_bfloat16 hi = __float2bfloat16(v);
        thi[(size_t)n * K + k] = hi;
        tlo[(size_t)n * K + k] = __float2bfloat16(v - __bfloat162float(hi));
    }
}

// ---------------- gemm1 (bf16x3 HMMA): h = cb@W1 + b1, + selu splits -------
__global__ void __launch_bounds__(256) gemm1_mma_k(const float* __restrict__ b1) {
    extern __shared__ char smem[];
    uint32_t sbase = smem_u32(smem);

    int tid = threadIdx.x;
    int wid = tid >> 5, lane = tid & 31;
    int bn = blockIdx.x * 128;
    int bm = blockIdx.y * 128;

    int wm = (wid & 3) * 32;
    int wn = (wid >> 2) * 64;

    float acc[2][8][4];
#pragma unroll
    for (int i = 0; i < 2; i++)
#pragma unroll
        for (int j = 0; j < 8; j++)
#pragma unroll
            for (int r = 0; r < 4; r++) acc[i][j][r] = 0.f;

    auto issue_stage = [&](int s) {
        int b = s & 1;
        int k0 = s * KC2;
        uint32_t buf = sbase + b * G2_STAGE;
#pragma unroll
        for (int r = 0; r < 2; r++) {
            int c = tid + 256 * r;
            int row = c >> 2, part = c & 3;
            uint32_t so = (uint32_t)(row * ROWB2 + part * 16);
            size_t goA = (size_t)(bm + row) * CDIM + k0 + part * 8;
            size_t goB = (size_t)(bn + row) * CDIM + k0 + part * 8;
            CP_ASYNC16(buf + so, g_cbhi + goA);
            CP_ASYNC16(buf + G2_OFF_ALO + so, g_cblo + goA);
            CP_ASYNC16(buf + G2_OFF_BHI + so, g_w1thi + goB);
            CP_ASYNC16(buf + G2_OFF_BLO + so, g_w1tlo + goB);
        }
    };

    issue_stage(0);
    CP_COMMIT();

    for (int s = 0; s < NSTG1; s++) {
        if (s + 1 < NSTG1) {
            issue_stage(s + 1);
            CP_COMMIT();
            CP_WAIT1();
        } else {
            CP_WAIT0();
        }
        __syncthreads();

        uint32_t buf = sbase + (s & 1) * G2_STAGE;
#pragma unroll
        for (int kk = 0; kk < 2; kk++) {
            int kb = kk * 32;
            uint32_t arow = (uint32_t)((wm + (lane & 15)) * ROWB2 + kb + (lane >> 4) * 16);
            uint32_t ahi0[4], ahi1[4], alo0[4], alo1[4];
            ldm_x4(ahi0, buf + arow);
            ldm_x4(ahi1, buf + arow + 16 * ROWB2);
            ldm_x4(alo0, buf + G2_OFF_ALO + arow);
            ldm_x4(alo1, buf + G2_OFF_ALO + arow + 16 * ROWB2);

            uint32_t brow_base =
                (uint32_t)((wn + (lane & 7)) * ROWB2 + kb + ((lane >> 3) & 1) * 16);
#pragma unroll
            for (int j = 0; j < 8; j++) {
                uint32_t bo = brow_base + (uint32_t)(j * 8 * ROWB2);
                uint32_t bhi[2], blo[2];
                ldm_x2(bhi, buf + G2_OFF_BHI + bo);
                ldm_x2(blo, buf + G2_OFF_BLO + bo);
                mma_bf16(acc[0][j], ahi0, bhi);
                mma_bf16(acc[0][j], ahi0, blo);
                mma_bf16(acc[0][j], alo0, bhi);
                mma_bf16(acc[1][j], ahi1, bhi);
                mma_bf16(acc[1][j], ahi1, blo);
                mma_bf16(acc[1][j], alo1, bhi);
            }
        }
        __syncthreads();
    }

    int q = lane >> 2, t = lane & 3;
#pragma unroll
    for (int i = 0; i < 2; i++) {
#pragma unroll
        for (int h = 0; h < 2; h++) {
            int m = bm + wm + i * 16 + h * 8 + q;
#pragma unroll
            for (int j = 0; j < 8; j++) {
#pragma unroll
                for (int e = 0; e < 2; e++) {
                    int n = bn + wn + j * 8 + 2 * t + e;
                    float v = acc[i][j][h * 2 + e] + b1[n];
                    g_h[(size_t)m * DIM + n] = v;
                    float sv = selu_f(v);
                    __nv_bfloat16 hi = __float2bfloat16(sv);
                    g_shi[(size_t)m * DIM + n] = hi;
                    g_slo[(size_t)m * DIM + n] =
                        __float2bfloat16(sv - __bfloat162float(hi));
                }
            }
        }
    }
}

// ---------------- gemm2 (bf16x3 HMMA): icb = h + selu(h)@W2 + b2 ----------
__global__ void __launch_bounds__(256) gemm2_mma_k(const float* __restrict__ b2) {
    extern __shared__ char smem[];
    uint32_t sbase = smem_u32(smem);

    int tid = threadIdx.x;
    int wid = tid >> 5, lane = tid & 31;
    int bn = blockIdx.x * 128;
    int bm = blockIdx.y * 128;

    int wm = (wid & 3) * 32;
    int wn = (wid >> 2) * 64;

    float acc[2][8][4];
#pragma unroll
    for (int i = 0; i < 2; i++)
#pragma unroll
        for (int j = 0; j < 8; j++)
#pragma unroll
            for (int r = 0; r < 4; r++) acc[i][j][r] = 0.f;

    auto issue_stage = [&](int s) {
        int b = s & 1;
        int k0 = s * KC2;
        uint32_t buf = sbase + b * G2_STAGE;
#pragma unroll
        for (int r = 0; r < 2; r++) {
            int c = tid + 256 * r;
            int row = c >> 2, part = c & 3;
            uint32_t so = (uint32_t)(row * ROWB2 + part * 16);
            size_t goA = (size_t)(bm + row) * DIM + k0 + part * 8;
            size_t goB = (size_t)(bn + row) * DIM + k0 + part * 8;
            CP_ASYNC16(buf + so, g_shi + goA);
            CP_ASYNC16(buf + G2_OFF_ALO + so, g_slo + goA);
            CP_ASYNC16(buf + G2_OFF_BHI + so, g_w2thi + goB);
            CP_ASYNC16(buf + G2_OFF_BLO + so, g_w2tlo + goB);
        }
    };

    issue_stage(0);
    CP_COMMIT();

    for (int s = 0; s < NSTG2; s++) {
        if (s + 1 < NSTG2) {
            issue_stage(s + 1);
            CP_COMMIT();
            CP_WAIT1();
        } else {
            CP_WAIT0();
        }
        __syncthreads();

        uint32_t buf = sbase + (s & 1) * G2_STAGE;
#pragma unroll
        for (int kk = 0; kk < 2; kk++) {
            int kb = kk * 32;
            uint32_t arow = (uint32_t)((wm + (lane & 15)) * ROWB2 + kb + (lane >> 4) * 16);
            uint32_t ahi0[4], ahi1[4], alo0[4], alo1[4];
            ldm_x4(ahi0, buf + arow);
            ldm_x4(ahi1, buf + arow + 16 * ROWB2);
            ldm_x4(alo0, buf + G2_OFF_ALO + arow);
            ldm_x4(alo1, buf + G2_OFF_ALO + arow + 16 * ROWB2);

            uint32_t brow_base =
                (uint32_t)((wn + (lane & 7)) * ROWB2 + kb + ((lane >> 3) & 1) * 16);
#pragma unroll
            for (int j = 0; j < 8; j++) {
                uint32_t bo = brow_base + (uint32_t)(j * 8 * ROWB2);
                uint32_t bhi[2], blo[2];
                ldm_x2(bhi, buf + G2_OFF_BHI + bo);
                ldm_x2(blo, buf + G2_OFF_BLO + bo);
                mma_bf16(acc[0][j], ahi0, bhi);
                mma_bf16(acc[0][j], ahi0, blo);
                mma_bf16(acc[0][j], alo0, bhi);
                mma_bf16(acc[1][j], ahi1, bhi);
                mma_bf16(acc[1][j], ahi1, blo);
                mma_bf16(acc[1][j], alo1, bhi);
            }
        }
        __syncthreads();
    }

    int q = lane >> 2, t = lane & 3;
    int part = blockIdx.x * 2 + (wn >> 6);
#pragma unroll
    for (int i = 0; i < 2; i++) {
#pragma unroll
        for (int h = 0; h < 2; h++) {
            int m = bm + wm + i * 16 + h * 8 + q;
            float ss = 0.f;
#pragma unroll
            for (int j = 0; j < 8; j++) {
#pragma unroll
                for (int e = 0; e < 2; e++) {
                    int n = bn + wn + j * 8 + 2 * t + e;
                    float v = (g_h[(size_t)m * DIM + n] + acc[i][j][h * 2 + e]) + b2[n];
                    g_icb[(size_t)m * DIM + n] = v;
                    ss += v * v;
                }
            }
            ss += __shfl_down_sync(0xffffffffu, ss, 1, 4);
            ss += __shfl_down_sync(0xffffffffu, ss, 2, 4);
            if (t == 0) g_ccpart[part * CSIZE + m] = ss;
        }
    }
}

// ---------------- cc finalize ----------------
__global__ void ccfin_k() {
    int i = blockIdx.x * 256 + threadIdx.x;
    float cc = 0.f;
#pragma unroll
    for (int p = 0; p < 8; p++) cc += g_ccpart[p * CSIZE + i];
    g_cc[i] = cc;
}

// ---------------- Phase 1: int8 dist GEMM + interval candidate filter ------
// CTA 128x128, 8 warps 32x64, m16n8k32.s8, 3 buffers, one sync per stage.
__global__ void __launch_bounds__(256, 2) dist_mma_k() {
    extern __shared__ char smem[];
    uint32_t sbase = smem_u32(smem);
    float* s_cc  = (float*)smem;          // [128]
    float* s_sc  = (float*)smem + 128;    // [128]
    float* s_l1c = (float*)smem + 256;    // [128]

    int tid = threadIdx.x;
    int wid = tid >> 5, lane = tid & 31;
    int bn = blockIdx.x * NT;
    int bm = blockIdx.y * MT;

    int wm = (wid & 3) * 32;
    int wn = (wid >> 2) * 64;

    if (tid < NT) {
        s_cc[tid] = g_cc[bn + tid];
        s_sc[tid] = g_sc[bn + tid];
        s_l1c[tid] = g_l1c[bn + tid];
    }

    int acc[2][8][4];
#pragma unroll
    for (int i = 0; i < 2; i++)
#pragma unroll
        for (int j = 0; j < 8; j++)
#pragma unroll
            for (int r = 0; r < 4; r++) acc[i][j][r] = 0;

    auto issue_stage = [&](int s, uint32_t buf) {
        int k0 = s * KCB;
#pragma unroll
        for (int r = 0; r < 2; r++) {
            int c = tid + 256 * r;                 // 0..511
            int row = c >> 2, part = c & 3;
            uint32_t so = (uint32_t)(row * ROWB + part * 16);
            CP_ASYNC16(buf + so, g_qx + (size_t)(bm + row) * DIM + k0 + part * 16);
            CP_ASYNC16(buf + OFF_B + so, g_qc + (size_t)(bn + row) * DIM + k0 + part * 16);
        }
    };

    uint32_t buf0 = sbase + SM_BUF0;
    issue_stage(0, buf0); CP_COMMIT();
    issue_stage(1, buf0 + SM_STAGE); CP_COMMIT();

    int bi = 0, ni = 2;
    int g = lane >> 3;
    uint32_t arow_l = (uint32_t)((wm + (lane & 15)) * ROWB + (lane >> 4) * 16);
    uint32_t brow_l = (uint32_t)((wn + (g >> 1) * 8 + (lane & 7)) * ROWB + (g & 1) * 16);

    for (int s = 0; s < NSTG; s++) {
        if (s + 1 < NSTG) CP_WAIT1(); else CP_WAIT0();
        __syncthreads();
        if (s + 2 < NSTG) {
            issue_stage(s + 2, buf0 + (uint32_t)ni * SM_STAGE);
            CP_COMMIT();
        }

        uint32_t buf = buf0 + (uint32_t)bi * SM_STAGE;
#pragma unroll
        for (int kk = 0; kk < 2; kk++) {
            int kb = kk * 32;
            uint32_t a0[4], a1[4];
            ldm_x4(a0, buf + arow_l + kb);
            ldm_x4(a1, buf + arow_l + kb + 16 * ROWB);

            uint32_t baddr = buf + OFF_B + brow_l + kb;
#pragma unroll
            for (int jp = 0; jp < 4; jp++) {
                uint32_t bfrag[4];
                ldm_x4(bfrag, baddr + (uint32_t)(jp * 16 * ROWB));
                mma_s8(acc[0][2 * jp + 0], a0, bfrag + 0);
                mma_s8(acc[0][2 * jp + 1], a0, bfrag + 2);
                mma_s8(acc[1][2 * jp + 0], a1, bfrag + 0);
                mma_s8(acc[1][2 * jp + 1], a1, bfrag + 2);
            }
        }
        bi++; if (bi == 3) bi = 0;
        ni++; if (ni == 3) ni = 0;
    }

    // -------- epilogue: interval filter --------
    int q = lane >> 2, t = lane & 3;
#pragma unroll
    for (int i = 0; i < 2; i++) {
#pragma unroll
        for (int h = 0; h < 2; h++) {
            int row = bm + wm + i * 16 + h * 8 + q;
            float xxv = g_xx[row];
            float sxm = g_sx[row];
            float l1xm = g_l1x[row];
            float d2s[16], es[16];
            float bestup = 3.4e38f;
#pragma unroll
            for (int j = 0; j < 8; j++) {
#pragma unroll
                for (int e = 0; e < 2; e++) {
                    int cidx = wn + j * 8 + 2 * t + e;
                    float sc = s_sc[cidx];
                    float dot = sxm * sc * (float)acc[i][j][h * 2 + e];
                    float d2 = xxv - 2.f * dot + s_cc[cidx];
                    float err = (0.5f * (sc * l1xm + sxm * s_l1c[cidx])
                                 + 128.f * sxm * sc) * 1.0625f + 1e-3f;
                    d2s[j * 2 + e] = d2;
                    es[j * 2 + e] = err;
                    bestup = fminf(bestup, d2 + err);
                }
            }
            unsigned int fb = ord_enc(bestup);
            unsigned int o1 = __shfl_xor_sync(0xffffffffu, fb, 1);
            fb = (o1 < fb) ? o1 : fb;
            unsigned int o2 = __shfl_xor_sync(0xffffffffu, fb, 2);
            fb = (o2 < fb) ? o2 : fb;
            unsigned int old = 0xFFFFFFFFu;
            if (t == 0) old = atomicMin(&g_rowmin[row], fb);
            old = __shfl_sync(0xffffffffu, old, lane & ~3);
            unsigned int run = (old < fb) ? old : fb;
            float thrv = ord_dec(run);
#pragma unroll
            for (int j = 0; j < 8; j++) {
#pragma unroll
                for (int e = 0; e < 2; e++) {
                    if (d2s[j * 2 + e] - es[j * 2 + e] <= thrv) {
                        unsigned int slot = atomicAdd(&g_ccount[row], 1u);
                        if (slot < CAP)
                            g_cand[row * CAP + slot] = bn + wn + j * 8 + 2 * t + e;
                    }
                }
            }
        }
    }
}

// ---------------- Phase 2 + finish: warp-parallel refine, rotation, loss ----
__global__ void refine_finish_k(const float* __restrict__ X, float* __restrict__ out,
                                int M, long long idx_off)
{
    int m = blockIdx.x;
    int tid = threadIdx.x;   // 128
    int wid = tid >> 5, lane = tid & 31;
    unsigned int cnt = g_ccount[m];
    float xxv = g_xx[m];

    __shared__ float sx[DIM];
    __shared__ unsigned long long wbest[4];
    __shared__ int s_idx;
    __shared__ float sb[16];

    float4 xv4 = *(const float4*)(X + (size_t)m * DIM + tid * 4);
    *(float4*)(sx + tid * 4) = xv4;
    __syncthreads();

    bool fullscan = (cnt == 0u) || (cnt > (unsigned)CAP);
    int n_iter = fullscan ? CSIZE : (int)cnt;

    unsigned long long best = ~0ULL;
    const float4* sx4 = (const float4*)sx;
    for (int s = wid; s < n_iter; s += 4) {
        int c = fullscan ? s : g_cand[m * CAP + s];
        const float4* cr = (const float4*)(g_icb + (size_t)c * DIM);
        float p = 0.f;
#pragma unroll
        for (int i = 0; i < 4; i++) {
            float4 cv = cr[lane + 32 * i];
            float4 xs = sx4[lane + 32 * i];
            p += cv.x * xs.x + cv.y * xs.y + cv.z * xs.z + cv.w * xs.w;
        }
        for (int o = 16; o > 0; o >>= 1) p += __shfl_down_sync(0xffffffffu, p, o);
        if (lane == 0) {
            float d2 = __fadd_rn(__fadd_rn(xxv, __fmul_rn(p, -2.0f)), g_cc[c]);
            unsigned long long key =
                ((unsigned long long)ord_enc(d2) << 32) | (unsigned)c;
            if (key < best) best = key;
        }
    }
    if (lane == 0) wbest[wid] = best;
    __syncthreads();
    if (tid == 0) {
        unsigned long long b = wbest[0];
#pragma unroll
        for (int w = 1; w < 4; w++) if (wbest[w] < b) b = wbest[w];
        s_idx = (int)(b & 0xffffffffu);
    }
    __syncthreads();
    int idx = s_idx;

    float4 qv4 = *(const float4*)(g_icb + (size_t)idx * DIM + tid * 4);
    float xv[4] = {xv4.x, xv4.y, xv4.z, xv4.w};
    float qv[4] = {qv4.x, qv4.y, qv4.z, qv4.w};

    float sx2 = 0.f, sq2 = 0.f, sd2 = 0.f;
#pragma unroll
    for (int i = 0; i < 4; i++) {
        sx2 += xv[i] * xv[i];
        sq2 += qv[i] * qv[i];
        float df = xv[i] - qv[i];
        sd2 += df * df;
    }

    {
        float v0 = sx2, v1 = sq2, v2 = sd2;
        for (int o = 16; o > 0; o >>= 1) {
            v0 += __shfl_down_sync(0xffffffffu, v0, o);
            v1 += __shfl_down_sync(0xffffffffu, v1, o);
            v2 += __shfl_down_sync(0xffffffffu, v2, o);
        }
        if (lane == 0) { sb[wid] = v0; sb[4 + wid] = v1; sb[8 + wid] = v2; }
        __syncthreads();
        sx2 = sb[0] + sb[1] + sb[2] + sb[3];
        sq2 = sb[4] + sb[5] + sb[6] + sb[7];
        sd2 = sb[8] + sb[9] + sb[10] + sb[11];
        __syncthreads();
    }

    float ns = sqrtf(sx2), nt = sqrtf(sq2);
    float ins = 1.f / fmaxf(ns, EPSV);
    float inv_t = 1.f / fmaxf(nt, EPSV);

    float wv[4];
    float sw2 = 0.f, sxw = 0.f;
#pragma unroll
    for (int i = 0; i < 4; i++) {
        float w = xv[i] * ins + qv[i] * inv_t;
        wv[i] = w;
        sw2 += w * w;
        sxw += xv[i] * w;
    }
    {
        float v0 = sw2, v1 = sxw;
        for (int o = 16; o > 0; o >>= 1) {
            v0 += __shfl_down_sync(0xffffffffu, v0, o);
            v1 += __shfl_down_sync(0xffffffffu, v1, o);
        }
        if (lane == 0) { sb[wid] = v0; sb[4 + wid] = v1; }
        __syncthreads();
        sw2 = sb[0] + sb[1] + sb[2] + sb[3];
        sxw = sb[4] + sb[5] + sb[6] + sb[7];
        __syncthreads();
    }

    float iwn = 1.f / fmaxf(sqrtf(sw2), EPSV);
    float xdw = sxw * iwn;
    float xdu = sx2 * ins;
    float scl = nt * ins;

    float4 o4;
    float ov[4];
#pragma unroll
    for (int i = 0; i < 4; i++) {
        float r = xv[i] - 2.f * xdw * (wv[i] * iwn) + 2.f * xdu * (qv[i] * inv_t);
        ov[i] = r * scl;
    }
    o4.x = ov[0]; o4.y = ov[1]; o4.z = ov[2]; o4.w = ov[3];
    *(float4*)(out + (size_t)m * DIM + tid * 4) = o4;

    if (tid == 0) {
        g_rowloss[m] = sd2;
        if (idx_off >= 0) out[idx_off + m] = (float)idx;
    }
}

__global__ void loss_k(float* __restrict__ out, int M, long long pos) {
    int tid = threadIdx.x;
    float s = 0.f;
    for (int i = tid; i < M; i += 256) s += g_rowloss[i];
    for (int o = 16; o > 0; o >>= 1) s += __shfl_down_sync(0xffffffffu, s, o);
    __shared__ float sb[8];
    if ((tid & 31) == 0) sb[tid >> 5] = s;
    __syncthreads();
    if (tid == 0) {
        float t = 0.f;
        for (int i = 0; i < 8; i++) t += sb[i];
        if (pos >= 0) out[pos] = 1.25f * t / (float)((size_t)M * DIM);
    }
}

// ---------------- host launcher ----------------
extern "C" void kernel_launch(void* const* d_in, const int* in_sizes, int n_in,
                              void* d_out, int out_size)
{
    const float* x  = (const float*)d_in[0];
    const float* cb = (const float*)d_in[1];
    const float* W1 = (const float*)d_in[2];
    const float* b1 = (const float*)d_in[3];
    const float* W2 = (const float*)d_in[4];
    const float* b2 = (const float*)d_in[5];
    float* out = (float*)d_out;

    int M = in_sizes[0] / DIM;
    long long NQ = (long long)M * DIM;

    long long idx_off = (out_size >= NQ + M) ? NQ : -1;
    long long loss_pos = -1;
    if (out_size >= NQ + M + 1) loss_pos = NQ + M;
    else if (out_size == NQ + 1) loss_pos = NQ;

    __nv_bfloat16 *p_w1thi, *p_w1tlo, *p_w2thi, *p_w2tlo;
    cudaGetSymbolAddress((void**)&p_w1thi, g_w1thi);
    cudaGetSymbolAddress((void**)&p_w1tlo, g_w1tlo);
    cudaGetSymbolAddress((void**)&p_w2thi, g_w2thi);
    cudaGetSymbolAddress((void**)&p_w2tlo, g_w2tlo);

    cudaFuncSetAttribute(dist_mma_k, cudaFuncAttributeMaxDynamicSharedMemorySize, SM_TOTAL);
    cudaFuncSetAttribute(gemm1_mma_k, cudaFuncAttributeMaxDynamicSharedMemorySize, G2_TOTAL);
    cudaFuncSetAttribute(gemm2_mma_k, cudaFuncAttributeMaxDynamicSharedMemorySize, G2_TOTAL);

    cudaMemsetAsync(d_out, 0, (size_t)out_size * sizeof(float));

    prep_x_k<<<M, 128>>>(x);
    cbprep_k<<<CSIZE * CDIM / 1024, 256>>>(cb);
    wtprep_k<<<dim3(DIM / 32, CDIM / 32), dim3(32, 8)>>>(W1, p_w1thi, p_w1tlo, CDIM, DIM);
    wtprep_k<<<dim3(DIM / 32, DIM / 32), dim3(32, 8)>>>(W2, p_w2thi, p_w2tlo, DIM, DIM);

    gemm1_mma_k<<<dim3(DIM / 128, CSIZE / 128), 256, G2_TOTAL>>>(b1);
    gemm2_mma_k<<<dim3(DIM / 128, CSIZE / 128), 256, G2_TOTAL>>>(b2);
    ccfin_k<<<CSIZE / 256, 256>>>();
    cprep_k<<<CSIZE, 128>>>();

    dist_mma_k<<<dim3(CSIZE / NT, M / MT), 256, SM_TOTAL>>>();

    refine_finish_k<<<M, 128>>>(x, out, M, idx_off);
    loss_k<<<1, 256>>>(out, M, loss_pos);
}

// round 16
// speedup vs baseline: 2.0231x; 2.0231x over previous
#include <cuda_runtime.h>
#include <cuda_bf16.h>
#include <cstdint>
#include <math.h>

#define DIM   512
#define CDIM  128
#define CSIZE 8192
#define MMAX  16384
#define EPSV  1e-6f
#define CAP   64

// ---- dist kernel tiling: KC=64, 3 buffers, single sync ----
#define MT 128
#define NT 128
#define KC 64
#define NSTG (DIM / KC)           // 8
#define ROWB 144                  // 64 bf16 = 128B + 16B pad (conflict-free)
#define BUFSZ (128 * ROWB)        // 18432
#define OFF_B BUFSZ
#define SM_STAGE (2 * BUFSZ)      // 36864
#define SM_BUF0 1024              // cc tile
#define SM_TOTAL (SM_BUF0 + 3 * SM_STAGE)   // 111616

// ---- bf16x3 transform-GEMM tiling (shared by gemm1/gemm2) ----
#define ROWB2 80
#define BUFSZ2 (128 * ROWB2)
#define G2_OFF_ALO (1 * BUFSZ2)
#define G2_OFF_BHI (2 * BUFSZ2)
#define G2_OFF_BLO (3 * BUFSZ2)
#define G2_STAGE (4 * BUFSZ2)
#define G2_TOTAL (2 * G2_STAGE)
#define KC2 32
#define NSTG2 (DIM / KC2)         // 16 (gemm2)
#define NSTG1 (CDIM / KC2)        // 4  (gemm1)

// ---------------- device scratch ----------------
__device__ float g_h[CSIZE * DIM];
__device__ float g_icb[CSIZE * DIM];
__device__ float g_cc[CSIZE];
__device__ float g_ccpart[8 * CSIZE];
__device__ float g_xx[MMAX];
__device__ float g_rowloss[MMAX];
__device__ __nv_bfloat16 g_xhi[MMAX * DIM];
__device__ __nv_bfloat16 g_chi[CSIZE * DIM];
__device__ __nv_bfloat16 g_shi[CSIZE * DIM];     // selu(h) hi
__device__ __nv_bfloat16 g_slo[CSIZE * DIM];     // selu(h) lo
__device__ __nv_bfloat16 g_cbhi[CSIZE * CDIM];   // cb hi
__device__ __nv_bfloat16 g_cblo[CSIZE * CDIM];   // cb lo
__device__ __nv_bfloat16 g_w1thi[DIM * CDIM];    // W1^T hi [n][k]
__device__ __nv_bfloat16 g_w1tlo[DIM * CDIM];    // W1^T lo
__device__ __nv_bfloat16 g_w2thi[DIM * DIM];     // W2^T hi [n][k]
__device__ __nv_bfloat16 g_w2tlo[DIM * DIM];     // W2^T lo
__device__ unsigned int g_rowmin[MMAX];
__device__ unsigned int g_ccount[MMAX];
__device__ int g_cand[MMAX * CAP];
__device__ unsigned int g_maxcc_u;

// ---------------- helpers ----------------
__device__ __forceinline__ uint32_t smem_u32(const void* p) {
    uint32_t a;
    asm("{ .reg .u64 t; cvta.to.shared.u64 t, %1; cvt.u32.u64 %0, t; }"
        : "=r"(a) : "l"(p));
    return a;
}

#define CP_ASYNC16(dst, src) \
    asm volatile("cp.async.cg.shared.global [%0], [%1], 16;" :: "r"(dst), "l"(src))
#define CP_COMMIT() asm volatile("cp.async.commit_group;" ::: "memory")
#define CP_WAIT1() asm volatile("cp.async.wait_group 1;" ::: "memory")
#define CP_WAIT0() asm volatile("cp.async.wait_group 0;" ::: "memory")

__device__ __forceinline__ void ldm_x4(uint32_t* r, uint32_t addr) {
    asm volatile("ldmatrix.sync.aligned.m8n8.x4.shared.b16 {%0,%1,%2,%3}, [%4];"
                 : "=r"(r[0]), "=r"(r[1]), "=r"(r[2]), "=r"(r[3]) : "r"(addr));
}
__device__ __forceinline__ void ldm_x2(uint32_t* r, uint32_t addr) {
    asm volatile("ldmatrix.sync.aligned.m8n8.x2.shared.b16 {%0,%1}, [%2];"
                 : "=r"(r[0]), "=r"(r[1]) : "r"(addr));
}
__device__ __forceinline__ void mma_bf16(float* c, const uint32_t* a, const uint32_t* b) {
    asm volatile(
        "mma.sync.aligned.m16n8k16.row.col.f32.bf16.bf16.f32 "
        "{%0,%1,%2,%3}, {%4,%5,%6,%7}, {%8,%9}, {%0,%1,%2,%3};"
        : "+f"(c[0]), "+f"(c[1]), "+f"(c[2]), "+f"(c[3])
        : "r"(a[0]), "r"(a[1]), "r"(a[2]), "r"(a[3]), "r"(b[0]), "r"(b[1]));
}

__device__ __forceinline__ unsigned int ord_enc(float f) {
    unsigned int u = __float_as_uint(f);
    return (u & 0x80000000u) ? ~u : (u | 0x80000000u);
}
__device__ __forceinline__ float ord_dec(unsigned int e) {
    unsigned int u = (e & 0x80000000u) ? (e & 0x7fffffffu) : ~e;
    return __uint_as_float(u);
}

__device__ __forceinline__ float selu_f(float z) {
    const float a = 1.6732632423543772f;
    const float s = 1.0507009873554805f;
    return s * (z > 0.f ? z : a * expm1f(z));
}

// ---------------- prep_x: xx + xhi + init state (float4 path) ----------------
__global__ void prep_x_k(const float* __restrict__ X) {
    int m = blockIdx.x;
    int tid = threadIdx.x;     // 128
    float4 v = *(const float4*)(X + (size_t)m * DIM + tid * 4);
    __nv_bfloat162 h0(__float2bfloat16(v.x), __float2bfloat16(v.y));
    __nv_bfloat162 h1(__float2bfloat16(v.z), __float2bfloat16(v.w));
    __nv_bfloat16* ho = g_xhi + (size_t)m * DIM + tid * 4;
    *(__nv_bfloat162*)ho = h0;
    *(__nv_bfloat162*)(ho + 2) = h1;

    float s = v.x * v.x + v.y * v.y + v.z * v.z + v.w * v.w;
    for (int o = 16; o > 0; o >>= 1) s += __shfl_down_sync(0xffffffffu, s, o);
    __shared__ float sb[4];
    if ((tid & 31) == 0) sb[tid >> 5] = s;
    __syncthreads();
    if (tid == 0) {
        g_xx[m] = sb[0] + sb[1] + sb[2] + sb[3];
        g_rowmin[m] = 0xFFFFFFFFu;
        g_ccount[m] = 0u;
        if (m == 0) g_maxcc_u = 0u;
    }
}

// ---------------- cb bf16 hi/lo split ----------------
__global__ void cbprep_k(const float* __restrict__ cb) {
    int i = (blockIdx.x * 256 + threadIdx.x) * 4;
    float4 v = *(const float4*)(cb + i);
    float vv[4] = {v.x, v.y, v.z, v.w};
#pragma unroll
    for (int q = 0; q < 4; q++) {
        __nv_bfloat16 hi = __float2bfloat16(vv[q]);
        g_cbhi[i + q] = hi;
        g_cblo[i + q] = __float2bfloat16(vv[q] - __bfloat162float(hi));
    }
}

// ---------------- W transpose + bf16 split (generic) ----------------
__global__ void wtprep_k(const float* __restrict__ W, __nv_bfloat16* __restrict__ thi,
                         __nv_bfloat16* __restrict__ tlo, int K, int N) {
    __shared__ float t[32][33];
    int bx = blockIdx.x * 32, by = blockIdx.y * 32;
    int tx = threadIdx.x, ty = threadIdx.y;           // 32x8
#pragma unroll
    for (int i = 0; i < 4; i++)
        t[ty + i * 8][tx] = W[(size_t)(by + ty + i * 8) * N + bx + tx];
    __syncthreads();
#pragma unroll
    for (int i = 0; i < 4; i++) {
        int n = bx + ty + i * 8, k = by + tx;
        float v = t[tx][ty + i * 8];
        __nv_bfloat16 hi = __float2bfloat16(v);
        thi[(size_t)n * K + k] = hi;
        tlo[(size_t)n * K + k] = __float2bfloat16(v - __bfloat162float(hi));
    }
}

// ---------------- gemm1 (bf16x3 HMMA): h = cb@W1 + b1, + selu splits -------
__global__ void __launch_bounds__(256) gemm1_mma_k(const float* __restrict__ b1) {
    extern __shared__ char smem[];
    uint32_t sbase = smem_u32(smem);

    int tid = threadIdx.x;
    int wid = tid >> 5, lane = tid & 31;
    int bn = blockIdx.x * 128;
    int bm = blockIdx.y * 128;

    int wm = (wid & 3) * 32;
    int wn = (wid >> 2) * 64;

    float acc[2][8][4];
#pragma unroll
    for (int i = 0; i < 2; i++)
#pragma unroll
        for (int j = 0; j < 8; j++)
#pragma unroll
            for (int r = 0; r < 4; r++) acc[i][j][r] = 0.f;

    auto issue_stage = [&](int s) {
        int b = s & 1;
        int k0 = s * KC2;
        uint32_t buf = sbase + b * G2_STAGE;
#pragma unroll
        for (int r = 0; r < 2; r++) {
            int c = tid + 256 * r;
            int row = c >> 2, part = c & 3;
            uint32_t so = (uint32_t)(row * ROWB2 + part * 16);
            size_t goA = (size_t)(bm + row) * CDIM + k0 + part * 8;
            size_t goB = (size_t)(bn + row) * CDIM + k0 + part * 8;
            CP_ASYNC16(buf + so, g_cbhi + goA);
            CP_ASYNC16(buf + G2_OFF_ALO + so, g_cblo + goA);
            CP_ASYNC16(buf + G2_OFF_BHI + so, g_w1thi + goB);
            CP_ASYNC16(buf + G2_OFF_BLO + so, g_w1tlo + goB);
        }
    };

    issue_stage(0);
    CP_COMMIT();

    for (int s = 0; s < NSTG1; s++) {
        if (s + 1 < NSTG1) {
            issue_stage(s + 1);
            CP_COMMIT();
            CP_WAIT1();
        } else {
            CP_WAIT0();
        }
        __syncthreads();

        uint32_t buf = sbase + (s & 1) * G2_STAGE;
#pragma unroll
        for (int kk = 0; kk < 2; kk++) {
            int kb = kk * 32;
            uint32_t arow = (uint32_t)((wm + (lane & 15)) * ROWB2 + kb + (lane >> 4) * 16);
            uint32_t ahi0[4], ahi1[4], alo0[4], alo1[4];
            ldm_x4(ahi0, buf + arow);
            ldm_x4(ahi1, buf + arow + 16 * ROWB2);
            ldm_x4(alo0, buf + G2_OFF_ALO + arow);
            ldm_x4(alo1, buf + G2_OFF_ALO + arow + 16 * ROWB2);

            uint32_t brow_base =
                (uint32_t)((wn + (lane & 7)) * ROWB2 + kb + ((lane >> 3) & 1) * 16);
#pragma unroll
            for (int j = 0; j < 8; j++) {
                uint32_t bo = brow_base + (uint32_t)(j * 8 * ROWB2);
                uint32_t bhi[2], blo[2];
                ldm_x2(bhi, buf + G2_OFF_BHI + bo);
                ldm_x2(blo, buf + G2_OFF_BLO + bo);
                mma_bf16(acc[0][j], ahi0, bhi);
                mma_bf16(acc[0][j], ahi0, blo);
                mma_bf16(acc[0][j], alo0, bhi);
                mma_bf16(acc[1][j], ahi1, bhi);
                mma_bf16(acc[1][j], ahi1, blo);
                mma_bf16(acc[1][j], alo1, bhi);
            }
        }
        __syncthreads();
    }

    int q = lane >> 2, t = lane & 3;
#pragma unroll
    for (int i = 0; i < 2; i++) {
#pragma unroll
        for (int h = 0; h < 2; h++) {
            int m = bm + wm + i * 16 + h * 8 + q;
#pragma unroll
            for (int j = 0; j < 8; j++) {
#pragma unroll
                for (int e = 0; e < 2; e++) {
                    int n = bn + wn + j * 8 + 2 * t + e;
                    float v = acc[i][j][h * 2 + e] + b1[n];
                    g_h[(size_t)m * DIM + n] = v;
                    float sv = selu_f(v);
                    __nv_bfloat16 hi = __float2bfloat16(sv);
                    g_shi[(size_t)m * DIM + n] = hi;
                    g_slo[(size_t)m * DIM + n] =
                        __float2bfloat16(sv - __bfloat162float(hi));
                }
            }
        }
    }
}

// ---------------- gemm2 (bf16x3 HMMA): icb = h + selu(h)@W2 + b2 ----------
__global__ void __launch_bounds__(256) gemm2_mma_k(const float* __restrict__ b2) {
    extern __shared__ char smem[];
    uint32_t sbase = smem_u32(smem);

    int tid = threadIdx.x;
    int wid = tid >> 5, lane = tid & 31;
    int bn = blockIdx.x * 128;
    int bm = blockIdx.y * 128;

    int wm = (wid & 3) * 32;
    int wn = (wid >> 2) * 64;

    float acc[2][8][4];
#pragma unroll
    for (int i = 0; i < 2; i++)
#pragma unroll
        for (int j = 0; j < 8; j++)
#pragma unroll
            for (int r = 0; r < 4; r++) acc[i][j][r] = 0.f;

    auto issue_stage = [&](int s) {
        int b = s & 1;
        int k0 = s * KC2;
        uint32_t buf = sbase + b * G2_STAGE;
#pragma unroll
        for (int r = 0; r < 2; r++) {
            int c = tid + 256 * r;
            int row = c >> 2, part = c & 3;
            uint32_t so = (uint32_t)(row * ROWB2 + part * 16);
            size_t goA = (size_t)(bm + row) * DIM + k0 + part * 8;
            size_t goB = (size_t)(bn + row) * DIM + k0 + part * 8;
            CP_ASYNC16(buf + so, g_shi + goA);
            CP_ASYNC16(buf + G2_OFF_ALO + so, g_slo + goA);
            CP_ASYNC16(buf + G2_OFF_BHI + so, g_w2thi + goB);
            CP_ASYNC16(buf + G2_OFF_BLO + so, g_w2tlo + goB);
        }
    };

    issue_stage(0);
    CP_COMMIT();

    for (int s = 0; s < NSTG2; s++) {
        if (s + 1 < NSTG2) {
            issue_stage(s + 1);
            CP_COMMIT();
            CP_WAIT1();
        } else {
            CP_WAIT0();
        }
        __syncthreads();

        uint32_t buf = sbase + (s & 1) * G2_STAGE;
#pragma unroll
        for (int kk = 0; kk < 2; kk++) {
            int kb = kk * 32;
            uint32_t arow = (uint32_t)((wm + (lane & 15)) * ROWB2 + kb + (lane >> 4) * 16);
            uint32_t ahi0[4], ahi1[4], alo0[4], alo1[4];
            ldm_x4(ahi0, buf + arow);
            ldm_x4(ahi1, buf + arow + 16 * ROWB2);
            ldm_x4(alo0, buf + G2_OFF_ALO + arow);
            ldm_x4(alo1, buf + G2_OFF_ALO + arow + 16 * ROWB2);

            uint32_t brow_base =
                (uint32_t)((wn + (lane & 7)) * ROWB2 + kb + ((lane >> 3) & 1) * 16);
#pragma unroll
            for (int j = 0; j < 8; j++) {
                uint32_t bo = brow_base + (uint32_t)(j * 8 * ROWB2);
                uint32_t bhi[2], blo[2];
                ldm_x2(bhi, buf + G2_OFF_BHI + bo);
                ldm_x2(blo, buf + G2_OFF_BLO + bo);
                mma_bf16(acc[0][j], ahi0, bhi);
                mma_bf16(acc[0][j], ahi0, blo);
                mma_bf16(acc[0][j], alo0, bhi);
                mma_bf16(acc[1][j], ahi1, bhi);
                mma_bf16(acc[1][j], ahi1, blo);
                mma_bf16(acc[1][j], alo1, bhi);
            }
        }
        __syncthreads();
    }

    int q = lane >> 2, t = lane & 3;
    int part = blockIdx.x * 2 + (wn >> 6);
#pragma unroll
    for (int i = 0; i < 2; i++) {
#pragma unroll
        for (int h = 0; h < 2; h++) {
            int m = bm + wm + i * 16 + h * 8 + q;
            float ss = 0.f;
#pragma unroll
            for (int j = 0; j < 8; j++) {
#pragma unroll
                for (int e = 0; e < 2; e++) {
                    int n = bn + wn + j * 8 + 2 * t + e;
                    float v = (g_h[(size_t)m * DIM + n] + acc[i][j][h * 2 + e]) + b2[n];
                    g_icb[(size_t)m * DIM + n] = v;
                    g_chi[(size_t)m * DIM + n] = __float2bfloat16(v);
                    ss += v * v;
                }
            }
            ss += __shfl_down_sync(0xffffffffu, ss, 1, 4);
            ss += __shfl_down_sync(0xffffffffu, ss, 2, 4);
            if (t == 0) g_ccpart[part * CSIZE + m] = ss;
        }
    }
}

// ---------------- cc finalize ----------------
__global__ void ccfin_k() {
    int i = blockIdx.x * 256 + threadIdx.x;
    float cc = 0.f;
#pragma unroll
    for (int p = 0; p < 8; p++) cc += g_ccpart[p * CSIZE + i];
    g_cc[i] = cc;
    float mx = cc;
    for (int o = 16; o > 0; o >>= 1) mx = fmaxf(mx, __shfl_down_sync(0xffffffffu, mx, o));
    __shared__ float sb[8];
    int tid = threadIdx.x;
    if ((tid & 31) == 0) sb[tid >> 5] = mx;
    __syncthreads();
    if (tid == 0) {
        float t = sb[0];
#pragma unroll
        for (int k = 1; k < 8; k++) t = fmaxf(t, sb[k]);
        atomicMax(&g_maxcc_u, ord_enc(t));
    }
}

// ---------------- Phase 1: approx bf16 dist GEMM + candidate filter --------
__global__ void __launch_bounds__(256) dist_mma_k() {
    extern __shared__ char smem[];
    uint32_t sbase = smem_u32(smem);
    float* s_cc = (float*)smem;

    int tid = threadIdx.x;
    int wid = tid >> 5, lane = tid & 31;
    int bn = blockIdx.x * NT;
    int bm = blockIdx.y * MT;

    int wm = (wid & 3) * 32;
    int wn = (wid >> 2) * 64;

    if (tid < NT) s_cc[tid] = g_cc[bn + tid];
    float maxcc = ord_dec(g_maxcc_u);

    float acc[2][8][4];
#pragma unroll
    for (int i = 0; i < 2; i++)
#pragma unroll
        for (int j = 0; j < 8; j++)
#pragma unroll
            for (int r = 0; r < 4; r++) acc[i][j][r] = 0.f;

    auto issue_stage = [&](int s, uint32_t buf) {
        int k0 = s * KC;
#pragma unroll
        for (int r = 0; r < 4; r++) {
            int c = tid + 256 * r;                 // 0..1023
            int row = c >> 3, part = c & 7;
            uint32_t so = (uint32_t)(row * ROWB + part * 16);
            CP_ASYNC16(buf + so, g_xhi + (size_t)(bm + row) * DIM + k0 + part * 8);
            CP_ASYNC16(buf + OFF_B + so, g_chi + (size_t)(bn + row) * DIM + k0 + part * 8);
        }
    };

    uint32_t buf0 = sbase + SM_BUF0;
    issue_stage(0, buf0); CP_COMMIT();
    issue_stage(1, buf0 + SM_STAGE); CP_COMMIT();

    int bi = 0, ni = 2;
    int g = lane >> 3;
    uint32_t arow_l = (uint32_t)((wm + (lane & 15)) * ROWB + (lane >> 4) * 16);
    uint32_t brow_l = (uint32_t)((wn + (g >> 1) * 8 + (lane & 7)) * ROWB + (g & 1) * 16);

    for (int s = 0; s < NSTG; s++) {
        if (s + 1 < NSTG) CP_WAIT1(); else CP_WAIT0();
        __syncthreads();
        if (s + 2 < NSTG) {
            issue_stage(s + 2, buf0 + (uint32_t)ni * SM_STAGE);
            CP_COMMIT();
        }

        uint32_t buf = buf0 + (uint32_t)bi * SM_STAGE;
#pragma unroll
        for (int kk = 0; kk < 4; kk++) {
            int kb = kk * 32;
            uint32_t ahi0[4], ahi1[4];
            ldm_x4(ahi0, buf + arow_l + kb);
            ldm_x4(ahi1, buf + arow_l + kb + 16 * ROWB);

            uint32_t baddr = buf + OFF_B + brow_l + kb;
#pragma unroll
            for (int jp = 0; jp < 4; jp++) {
                uint32_t bfrag[4];
                ldm_x4(bfrag, baddr + (uint32_t)(jp * 16 * ROWB));
                mma_bf16(acc[0][2 * jp + 0], ahi0, bfrag + 0);
                mma_bf16(acc[0][2 * jp + 1], ahi0, bfrag + 2);
                mma_bf16(acc[1][2 * jp + 0], ahi1, bfrag + 0);
                mma_bf16(acc[1][2 * jp + 1], ahi1, bfrag + 2);
            }
        }
        bi++; if (bi == 3) bi = 0;
        ni++; if (ni == 3) ni = 0;
    }

    int q = lane >> 2, t = lane & 3;
#pragma unroll
    for (int i = 0; i < 2; i++) {
#pragma unroll
        for (int h = 0; h < 2; h++) {
            int row = bm + wm + i * 16 + h * 8 + q;
            float xxv = g_xx[row];
            float d2s[16];
            float best = 3.4e38f;
#pragma unroll
            for (int j = 0; j < 8; j++) {
#pragma unroll
                for (int e = 0; e < 2; e++) {
                    float dot = acc[i][j][h * 2 + e];
                    float d2 = __fadd_rn(__fadd_rn(xxv, __fmul_rn(dot, -2.0f)),
                                         s_cc[wn + j * 8 + 2 * t + e]);
                    d2s[j * 2 + e] = d2;
                    best = fminf(best, d2);
                }
            }
            unsigned int fb = ord_enc(best);
            unsigned int o1 = __shfl_xor_sync(0xffffffffu, fb, 1);
            fb = (o1 < fb) ? o1 : fb;
            unsigned int o2 = __shfl_xor_sync(0xffffffffu, fb, 2);
            fb = (o2 < fb) ? o2 : fb;
            unsigned int old = 0xFFFFFFFFu;
            if (t == 0) old = atomicMin(&g_rowmin[row], fb);
            old = __shfl_sync(0xffffffffu, old, lane & ~3);
            unsigned int run = (old < fb) ? old : fb;
            float thr = ord_dec(run) + (2.f * sqrtf(xxv * maxcc) * 0.0078125f + 0.01f);
#pragma unroll
            for (int j = 0; j < 8; j++) {
#pragma unroll
                for (int e = 0; e < 2; e++) {
                    if (d2s[j * 2 + e] < thr) {
                        unsigned int slot = atomicAdd(&g_ccount[row], 1u);
                        if (slot < CAP)
                            g_cand[row * CAP + slot] = bn + wn + j * 8 + 2 * t + e;
                    }
                }
            }
        }
    }
}

// ---------------- Phase 2 + finish: warp-parallel refine, rotation, loss ----
__global__ void refine_finish_k(const float* __restrict__ X, float* __restrict__ out,
                                int M, long long idx_off)
{
    int m = blockIdx.x;
    int tid = threadIdx.x;   // 128
    int wid = tid >> 5, lane = tid & 31;
    unsigned int cnt = g_ccount[m];
    float xxv = g_xx[m];

    __shared__ float sx[DIM];
    __shared__ unsigned long long wbest[4];
    __shared__ int s_idx;
    __shared__ float sb[16];

    // load x row (float4 per thread) and stash in smem
    float4 xv4 = *(const float4*)(X + (size_t)m * DIM + tid * 4);
    *(float4*)(sx + tid * 4) = xv4;
    __syncthreads();

    bool fullscan = (cnt == 0u) || (cnt > (unsigned)CAP);
    int n_iter = fullscan ? CSIZE : (int)cnt;

    // warp-parallel candidate scan: warp w handles s = w, w+4, ...
    unsigned long long best = ~0ULL;
    const float4* sx4 = (const float4*)sx;
    for (int s = wid; s < n_iter; s += 4) {
        int c = fullscan ? s : g_cand[m * CAP + s];
        const float4* cr = (const float4*)(g_icb + (size_t)c * DIM);
        float p = 0.f;
#pragma unroll
        for (int i = 0; i < 4; i++) {
            float4 cv = cr[lane + 32 * i];
            float4 xs = sx4[lane + 32 * i];
            p += cv.x * xs.x + cv.y * xs.y + cv.z * xs.z + cv.w * xs.w;
        }
        for (int o = 16; o > 0; o >>= 1) p += __shfl_down_sync(0xffffffffu, p, o);
        if (lane == 0) {
            float d2 = __fadd_rn(__fadd_rn(xxv, __fmul_rn(p, -2.0f)), g_cc[c]);
            unsigned long long key =
                ((unsigned long long)ord_enc(d2) << 32) | (unsigned)c;
            if (key < best) best = key;
        }
    }
    if (lane == 0) wbest[wid] = best;
    __syncthreads();
    if (tid == 0) {
        unsigned long long b = wbest[0];
#pragma unroll
        for (int w = 1; w < 4; w++) if (wbest[w] < b) b = wbest[w];
        s_idx = (int)(b & 0xffffffffu);
    }
    __syncthreads();
    int idx = s_idx;

    // ---- rotation + loss (float4 per-thread layout) ----
    float4 qv4 = *(const float4*)(g_icb + (size_t)idx * DIM + tid * 4);
    float xv[4] = {xv4.x, xv4.y, xv4.z, xv4.w};
    float qv[4] = {qv4.x, qv4.y, qv4.z, qv4.w};

    float sx2 = 0.f, sq2 = 0.f, sd2 = 0.f;
#pragma unroll
    for (int i = 0; i < 4; i++) {
        sx2 += xv[i] * xv[i];
        sq2 += qv[i] * qv[i];
        float df = xv[i] - qv[i];
        sd2 += df * df;
    }

    {
        float v0 = sx2, v1 = sq2, v2 = sd2;
        for (int o = 16; o > 0; o >>= 1) {
            v0 += __shfl_down_sync(0xffffffffu, v0, o);
            v1 += __shfl_down_sync(0xffffffffu, v1, o);
            v2 += __shfl_down_sync(0xffffffffu, v2, o);
        }
        if (lane == 0) { sb[wid] = v0; sb[4 + wid] = v1; sb[8 + wid] = v2; }
        __syncthreads();
        sx2 = sb[0] + sb[1] + sb[2] + sb[3];
        sq2 = sb[4] + sb[5] + sb[6] + sb[7];
        sd2 = sb[8] + sb[9] + sb[10] + sb[11];
        __syncthreads();
    }

    float ns = sqrtf(sx2), nt = sqrtf(sq2);
    float ins = 1.f / fmaxf(ns, EPSV);
    float inv_t = 1.f / fmaxf(nt, EPSV);

    float wv[4];
    float sw2 = 0.f, sxw = 0.f;
#pragma unroll
    for (int i = 0; i < 4; i++) {
        float w = xv[i] * ins + qv[i] * inv_t;
        wv[i] = w;
        sw2 += w * w;
        sxw += xv[i] * w;
    }
    {
        float v0 = sw2, v1 = sxw;
        for (int o = 16; o > 0; o >>= 1) {
            v0 += __shfl_down_sync(0xffffffffu, v0, o);
            v1 += __shfl_down_sync(0xffffffffu, v1, o);
        }
        if (lane == 0) { sb[wid] = v0; sb[4 + wid] = v1; }
        __syncthreads();
        sw2 = sb[0] + sb[1] + sb[2] + sb[3];
        sxw = sb[4] + sb[5] + sb[6] + sb[7];
        __syncthreads();
    }

    float iwn = 1.f / fmaxf(sqrtf(sw2), EPSV);
    float xdw = sxw * iwn;
    float xdu = sx2 * ins;
    float scl = nt * ins;

    float4 o4;
    float ov[4];
#pragma unroll
    for (int i = 0; i < 4; i++) {
        float r = xv[i] - 2.f * xdw * (wv[i] * iwn) + 2.f * xdu * (qv[i] * inv_t);
        ov[i] = r * scl;
    }
    o4.x = ov[0]; o4.y = ov[1]; o4.z = ov[2]; o4.w = ov[3];
    *(float4*)(out + (size_t)m * DIM + tid * 4) = o4;

    if (tid == 0) {
        g_rowloss[m] = sd2;
        if (idx_off >= 0) out[idx_off + m] = (float)idx;
    }
}

__global__ void loss_k(float* __restrict__ out, int M, long long pos) {
    int tid = threadIdx.x;
    float s = 0.f;
    for (int i = tid; i < M; i += 256) s += g_rowloss[i];
    for (int o = 16; o > 0; o >>= 1) s += __shfl_down_sync(0xffffffffu, s, o);
    __shared__ float sb[8];
    if ((tid & 31) == 0) sb[tid >> 5] = s;
    __syncthreads();
    if (tid == 0) {
        float t = 0.f;
        for (int i = 0; i < 8; i++) t += sb[i];
        if (pos >= 0) out[pos] = 1.25f * t / (float)((size_t)M * DIM);
    }
}

// ---------------- host launcher ----------------
extern "C" void kernel_launch(void* const* d_in, const int* in_sizes, int n_in,
                              void* d_out, int out_size)
{
    const float* x  = (const float*)d_in[0];
    const float* cb = (const float*)d_in[1];
    const float* W1 = (const float*)d_in[2];
    const float* b1 = (const float*)d_in[3];
    const float* W2 = (const float*)d_in[4];
    const float* b2 = (const float*)d_in[5];
    float* out = (float*)d_out;

    int M = in_sizes[0] / DIM;
    long long NQ = (long long)M * DIM;

    long long idx_off = (out_size >= NQ + M) ? NQ : -1;
    long long loss_pos = -1;
    if (out_size >= NQ + M + 1) loss_pos = NQ + M;
    else if (out_size == NQ + 1) loss_pos = NQ;

    __nv_bfloat16 *p_w1thi, *p_w1tlo, *p_w2thi, *p_w2tlo;
    cudaGetSymbolAddress((void**)&p_w1thi, g_w1thi);
    cudaGetSymbolAddress((void**)&p_w1tlo, g_w1tlo);
    cudaGetSymbolAddress((void**)&p_w2thi, g_w2thi);
    cudaGetSymbolAddress((void**)&p_w2tlo, g_w2tlo);

    cudaFuncSetAttribute(dist_mma_k, cudaFuncAttributeMaxDynamicSharedMemorySize, SM_TOTAL);
    cudaFuncSetAttribute(gemm1_mma_k, cudaFuncAttributeMaxDynamicSharedMemorySize, G2_TOTAL);
    cudaFuncSetAttribute(gemm2_mma_k, cudaFuncAttributeMaxDynamicSharedMemorySize, G2_TOTAL);

    cudaMemsetAsync(d_out, 0, (size_t)out_size * sizeof(float));

    prep_x_k<<<M, 128>>>(x);
    cbprep_k<<<CSIZE * CDIM / 1024, 256>>>(cb);
    wtprep_k<<<dim3(DIM / 32, CDIM / 32), dim3(32, 8)>>>(W1, p_w1thi, p_w1tlo, CDIM, DIM);
    wtprep_k<<<dim3(DIM / 32, DIM / 32), dim3(32, 8)>>>(W2, p_w2thi, p_w2tlo, DIM, DIM);

    gemm1_mma_k<<<dim3(DIM / 128, CSIZE / 128), 256, G2_TOTAL>>>(b1);
    gemm2_mma_k<<<dim3(DIM / 128, CSIZE / 128), 256, G2_TOTAL>>>(b2);
    ccfin_k<<<CSIZE / 256, 256>>>();

    dist_mma_k<<<dim3(CSIZE / NT, M / MT), 256, SM_TOTAL>>>();

    refine_finish_k<<<M, 128>>>(x, out, M, idx_off);
    loss_k<<<1, 256>>>(out, M, loss_pos);
}

// round 17
// speedup vs baseline: 2.0963x; 1.0362x over previous
#include <cuda_runtime.h>
#include <cuda_bf16.h>
#include <cstdint>
#include <math.h>

#define DIM   512
#define CDIM  128
#define CSIZE 8192
#define MMAX  16384
#define EPSV  1e-6f
#define CAP   64

// ---- dist kernel tiling: KC=64, 2 buffers (occupancy 2), single sync ----
#define MT 128
#define NT 128
#define KC 64
#define NSTG (DIM / KC)           // 8
#define ROWB 144                  // 64 bf16 = 128B + 16B pad (conflict-free)
#define BUFSZ (128 * ROWB)        // 18432
#define OFF_B BUFSZ
#define SM_STAGE (2 * BUFSZ)      // 36864
#define SM_BUF0 1024              // cc tile
#define SM_TOTAL (SM_BUF0 + 2 * SM_STAGE)   // 74752 -> 2 CTAs/SM

// ---- bf16x3 transform-GEMM tiling (shared by gemm1/gemm2) ----
#define ROWB2 80
#define BUFSZ2 (128 * ROWB2)
#define G2_OFF_ALO (1 * BUFSZ2)
#define G2_OFF_BHI (2 * BUFSZ2)
#define G2_OFF_BLO (3 * BUFSZ2)
#define G2_STAGE (4 * BUFSZ2)
#define G2_TOTAL (2 * G2_STAGE)
#define KC2 32
#define NSTG2 (DIM / KC2)         // 16 (gemm2)
#define NSTG1 (CDIM / KC2)        // 4  (gemm1)

// ---------------- device scratch ----------------
__device__ float g_h[CSIZE * DIM];
__device__ float g_icb[CSIZE * DIM];
__device__ float g_cc[CSIZE];
__device__ float g_ccpart[8 * CSIZE];
__device__ float g_xx[MMAX];
__device__ float g_rowloss[MMAX];
__device__ __nv_bfloat16 g_xhi[MMAX * DIM];
__device__ __nv_bfloat16 g_chi[CSIZE * DIM];
__device__ __nv_bfloat16 g_shi[CSIZE * DIM];     // selu(h) hi
__device__ __nv_bfloat16 g_slo[CSIZE * DIM];     // selu(h) lo
__device__ __nv_bfloat16 g_cbhi[CSIZE * CDIM];   // cb hi
__device__ __nv_bfloat16 g_cblo[CSIZE * CDIM];   // cb lo
__device__ __nv_bfloat16 g_w1thi[DIM * CDIM];    // W1^T hi [n][k]
__device__ __nv_bfloat16 g_w1tlo[DIM * CDIM];    // W1^T lo
__device__ __nv_bfloat16 g_w2thi[DIM * DIM];     // W2^T hi [n][k]
__device__ __nv_bfloat16 g_w2tlo[DIM * DIM];     // W2^T lo
__device__ unsigned int g_rowmin[MMAX];
__device__ unsigned int g_ccount[MMAX];
__device__ int g_cand[MMAX * CAP];
__device__ unsigned int g_maxcc_u;

// ---------------- helpers ----------------
__device__ __forceinline__ uint32_t smem_u32(const void* p) {
    uint32_t a;
    asm("{ .reg .u64 t; cvta.to.shared.u64 t, %1; cvt.u32.u64 %0, t; }"
        : "=r"(a) : "l"(p));
    return a;
}

#define CP_ASYNC16(dst, src) \
    asm volatile("cp.async.cg.shared.global [%0], [%1], 16;" :: "r"(dst), "l"(src))
#define CP_COMMIT() asm volatile("cp.async.commit_group;" ::: "memory")
#define CP_WAIT1() asm volatile("cp.async.wait_group 1;" ::: "memory")
#define CP_WAIT0() asm volatile("cp.async.wait_group 0;" ::: "memory")

__device__ __forceinline__ void ldm_x4(uint32_t* r, uint32_t addr) {
    asm volatile("ldmatrix.sync.aligned.m8n8.x4.shared.b16 {%0,%1,%2,%3}, [%4];"
                 : "=r"(r[0]), "=r"(r[1]), "=r"(r[2]), "=r"(r[3]) : "r"(addr));
}
__device__ __forceinline__ void ldm_x2(uint32_t* r, uint32_t addr) {
    asm volatile("ldmatrix.sync.aligned.m8n8.x2.shared.b16 {%0,%1}, [%2];"
                 : "=r"(r[0]), "=r"(r[1]) : "r"(addr));
}
__device__ __forceinline__ void mma_bf16(float* c, const uint32_t* a, const uint32_t* b) {
    asm volatile(
        "mma.sync.aligned.m16n8k16.row.col.f32.bf16.bf16.f32 "
        "{%0,%1,%2,%3}, {%4,%5,%6,%7}, {%8,%9}, {%0,%1,%2,%3};"
        : "+f"(c[0]), "+f"(c[1]), "+f"(c[2]), "+f"(c[3])
        : "r"(a[0]), "r"(a[1]), "r"(a[2]), "r"(a[3]), "r"(b[0]), "r"(b[1]));
}

__device__ __forceinline__ unsigned int ord_enc(float f) {
    unsigned int u = __float_as_uint(f);
    return (u & 0x80000000u) ? ~u : (u | 0x80000000u);
}
__device__ __forceinline__ float ord_dec(unsigned int e) {
    unsigned int u = (e & 0x80000000u) ? (e & 0x7fffffffu) : ~e;
    return __uint_as_float(u);
}

__device__ __forceinline__ float selu_f(float z) {
    const float a = 1.6732632423543772f;
    const float s = 1.0507009873554805f;
    return s * (z > 0.f ? z : a * expm1f(z));
}

// ---------------- prep_x: xx + xhi + init state (float4 path) ----------------
__global__ void prep_x_k(const float* __restrict__ X) {
    int m = blockIdx.x;
    int tid = threadIdx.x;     // 128
    float4 v = *(const float4*)(X + (size_t)m * DIM + tid * 4);
    __nv_bfloat162 h0(__float2bfloat16(v.x), __float2bfloat16(v.y));
    __nv_bfloat162 h1(__float2bfloat16(v.z), __float2bfloat16(v.w));
    __nv_bfloat16* ho = g_xhi + (size_t)m * DIM + tid * 4;
    *(__nv_bfloat162*)ho = h0;
    *(__nv_bfloat162*)(ho + 2) = h1;

    float s = v.x * v.x + v.y * v.y + v.z * v.z + v.w * v.w;
    for (int o = 16; o > 0; o >>= 1) s += __shfl_down_sync(0xffffffffu, s, o);
    __shared__ float sb[4];
    if ((tid & 31) == 0) sb[tid >> 5] = s;
    __syncthreads();
    if (tid == 0) {
        g_xx[m] = sb[0] + sb[1] + sb[2] + sb[3];
        g_rowmin[m] = 0xFFFFFFFFu;
        g_ccount[m] = 0u;
        if (m == 0) g_maxcc_u = 0u;
    }
}

// ---------------- cb bf16 hi/lo split ----------------
__global__ void cbprep_k(const float* __restrict__ cb) {
    int i = (blockIdx.x * 256 + threadIdx.x) * 4;
    float4 v = *(const float4*)(cb + i);
    float vv[4] = {v.x, v.y, v.z, v.w};
#pragma unroll
    for (int q = 0; q < 4; q++) {
        __nv_bfloat16 hi = __float2bfloat16(vv[q]);
        g_cbhi[i + q] = hi;
        g_cblo[i + q] = __float2bfloat16(vv[q] - __bfloat162float(hi));
    }
}

// ---------------- W transpose + bf16 split (generic) ----------------
__global__ void wtprep_k(const float* __restrict__ W, __nv_bfloat16* __restrict__ thi,
                         __nv_bfloat16* __restrict__ tlo, int K, int N) {
    __shared__ float t[32][33];
    int bx = blockIdx.x * 32, by = blockIdx.y * 32;
    int tx = threadIdx.x, ty = threadIdx.y;           // 32x8
#pragma unroll
    for (int i = 0; i < 4; i++)
        t[ty + i * 8][tx] = W[(size_t)(by + ty + i * 8) * N + bx + tx];
    __syncthreads();
#pragma unroll
    for (int i = 0; i < 4; i++) {
        int n = bx + ty + i * 8, k = by + tx;
        float v = t[tx][ty + i * 8];
        __nv_bfloat16 hi = __float2bfloat16(v);
        thi[(size_t)n * K + k] = hi;
        tlo[(size_t)n * K + k] = __float2bfloat16(v - __bfloat162float(hi));
    }
}

// ---------------- gemm1 (bf16x3 HMMA): h = cb@W1 + b1, + selu splits -------
__global__ void __launch_bounds__(256) gemm1_mma_k(const float* __restrict__ b1) {
    extern __shared__ char smem[];
    uint32_t sbase = smem_u32(smem);

    int tid = threadIdx.x;
    int wid = tid >> 5, lane = tid & 31;
    int bn = blockIdx.x * 128;
    int bm = blockIdx.y * 128;

    int wm = (wid & 3) * 32;
    int wn = (wid >> 2) * 64;

    float acc[2][8][4];
#pragma unroll
    for (int i = 0; i < 2; i++)
#pragma unroll
        for (int j = 0; j < 8; j++)
#pragma unroll
            for (int r = 0; r < 4; r++) acc[i][j][r] = 0.f;

    auto issue_stage = [&](int s) {
        int b = s & 1;
        int k0 = s * KC2;
        uint32_t buf = sbase + b * G2_STAGE;
#pragma unroll
        for (int r = 0; r < 2; r++) {
            int c = tid + 256 * r;
            int row = c >> 2, part = c & 3;
            uint32_t so = (uint32_t)(row * ROWB2 + part * 16);
            size_t goA = (size_t)(bm + row) * CDIM + k0 + part * 8;
            size_t goB = (size_t)(bn + row) * CDIM + k0 + part * 8;
            CP_ASYNC16(buf + so, g_cbhi + goA);
            CP_ASYNC16(buf + G2_OFF_ALO + so, g_cblo + goA);
            CP_ASYNC16(buf + G2_OFF_BHI + so, g_w1thi + goB);
            CP_ASYNC16(buf + G2_OFF_BLO + so, g_w1tlo + goB);
        }
    };

    issue_stage(0);
    CP_COMMIT();

    for (int s = 0; s < NSTG1; s++) {
        if (s + 1 < NSTG1) {
            issue_stage(s + 1);
            CP_COMMIT();
            CP_WAIT1();
        } else {
            CP_WAIT0();
        }
        __syncthreads();

        uint32_t buf = sbase + (s & 1) * G2_STAGE;
#pragma unroll
        for (int kk = 0; kk < 2; kk++) {
            int kb = kk * 32;
            uint32_t arow = (uint32_t)((wm + (lane & 15)) * ROWB2 + kb + (lane >> 4) * 16);
            uint32_t ahi0[4], ahi1[4], alo0[4], alo1[4];
            ldm_x4(ahi0, buf + arow);
            ldm_x4(ahi1, buf + arow + 16 * ROWB2);
            ldm_x4(alo0, buf + G2_OFF_ALO + arow);
            ldm_x4(alo1, buf + G2_OFF_ALO + arow + 16 * ROWB2);

            uint32_t brow_base =
                (uint32_t)((wn + (lane & 7)) * ROWB2 + kb + ((lane >> 3) & 1) * 16);
#pragma unroll
            for (int j = 0; j < 8; j++) {
                uint32_t bo = brow_base + (uint32_t)(j * 8 * ROWB2);
                uint32_t bhi[2], blo[2];
                ldm_x2(bhi, buf + G2_OFF_BHI + bo);
                ldm_x2(blo, buf + G2_OFF_BLO + bo);
                mma_bf16(acc[0][j], ahi0, bhi);
                mma_bf16(acc[0][j], ahi0, blo);
                mma_bf16(acc[0][j], alo0, bhi);
                mma_bf16(acc[1][j], ahi1, bhi);
                mma_bf16(acc[1][j], ahi1, blo);
                mma_bf16(acc[1][j], alo1, bhi);
            }
        }
        __syncthreads();
    }

    int q = lane >> 2, t = lane & 3;
#pragma unroll
    for (int i = 0; i < 2; i++) {
#pragma unroll
        for (int h = 0; h < 2; h++) {
            int m = bm + wm + i * 16 + h * 8 + q;
#pragma unroll
            for (int j = 0; j < 8; j++) {
#pragma unroll
                for (int e = 0; e < 2; e++) {
                    int n = bn + wn + j * 8 + 2 * t + e;
                    float v = acc[i][j][h * 2 + e] + b1[n];
                    g_h[(size_t)m * DIM + n] = v;
                    float sv = selu_f(v);
                    __nv_bfloat16 hi = __float2bfloat16(sv);
                    g_shi[(size_t)m * DIM + n] = hi;
                    g_slo[(size_t)m * DIM + n] =
                        __float2bfloat16(sv - __bfloat162float(hi));
                }
            }
        }
    }
}

// ---------------- gemm2 (bf16x3 HMMA): icb = h + selu(h)@W2 + b2 ----------
__global__ void __launch_bounds__(256) gemm2_mma_k(const float* __restrict__ b2) {
    extern __shared__ char smem[];
    uint32_t sbase = smem_u32(smem);

    int tid = threadIdx.x;
    int wid = tid >> 5, lane = tid & 31;
    int bn = blockIdx.x * 128;
    int bm = blockIdx.y * 128;

    int wm = (wid & 3) * 32;
    int wn = (wid >> 2) * 64;

    float acc[2][8][4];
#pragma unroll
    for (int i = 0; i < 2; i++)
#pragma unroll
        for (int j = 0; j < 8; j++)
#pragma unroll
            for (int r = 0; r < 4; r++) acc[i][j][r] = 0.f;

    auto issue_stage = [&](int s) {
        int b = s & 1;
        int k0 = s * KC2;
        uint32_t buf = sbase + b * G2_STAGE;
#pragma unroll
        for (int r = 0; r < 2; r++) {
            int c = tid + 256 * r;
            int row = c >> 2, part = c & 3;
            uint32_t so = (uint32_t)(row * ROWB2 + part * 16);
            size_t goA = (size_t)(bm + row) * DIM + k0 + part * 8;
            size_t goB = (size_t)(bn + row) * DIM + k0 + part * 8;
            CP_ASYNC16(buf + so, g_shi + goA);
            CP_ASYNC16(buf + G2_OFF_ALO + so, g_slo + goA);
            CP_ASYNC16(buf + G2_OFF_BHI + so, g_w2thi + goB);
            CP_ASYNC16(buf + G2_OFF_BLO + so, g_w2tlo + goB);
        }
    };

    issue_stage(0);
    CP_COMMIT();

    for (int s = 0; s < NSTG2; s++) {
        if (s + 1 < NSTG2) {
            issue_stage(s + 1);
            CP_COMMIT();
            CP_WAIT1();
        } else {
            CP_WAIT0();
        }
        __syncthreads();

        uint32_t buf = sbase + (s & 1) * G2_STAGE;
#pragma unroll
        for (int kk = 0; kk < 2; kk++) {
            int kb = kk * 32;
            uint32_t arow = (uint32_t)((wm + (lane & 15)) * ROWB2 + kb + (lane >> 4) * 16);
            uint32_t ahi0[4], ahi1[4], alo0[4], alo1[4];
            ldm_x4(ahi0, buf + arow);
            ldm_x4(ahi1, buf + arow + 16 * ROWB2);
            ldm_x4(alo0, buf + G2_OFF_ALO + arow);
            ldm_x4(alo1, buf + G2_OFF_ALO + arow + 16 * ROWB2);

            uint32_t brow_base =
                (uint32_t)((wn + (lane & 7)) * ROWB2 + kb + ((lane >> 3) & 1) * 16);
#pragma unroll
            for (int j = 0; j < 8; j++) {
                uint32_t bo = brow_base + (uint32_t)(j * 8 * ROWB2);
                uint32_t bhi[2], blo[2];
                ldm_x2(bhi, buf + G2_OFF_BHI + bo);
                ldm_x2(blo, buf + G2_OFF_BLO + bo);
                mma_bf16(acc[0][j], ahi0, bhi);
                mma_bf16(acc[0][j], ahi0, blo);
                mma_bf16(acc[0][j], alo0, bhi);
                mma_bf16(acc[1][j], ahi1, bhi);
                mma_bf16(acc[1][j], ahi1, blo);
                mma_bf16(acc[1][j], alo1, bhi);
            }
        }
        __syncthreads();
    }

    int q = lane >> 2, t = lane & 3;
    int part = blockIdx.x * 2 + (wn >> 6);
#pragma unroll
    for (int i = 0; i < 2; i++) {
#pragma unroll
        for (int h = 0; h < 2; h++) {
            int m = bm + wm + i * 16 + h * 8 + q;
            float ss = 0.f;
#pragma unroll
            for (int j = 0; j < 8; j++) {
#pragma unroll
                for (int e = 0; e < 2; e++) {
                    int n = bn + wn + j * 8 + 2 * t + e;
                    float v = (g_h[(size_t)m * DIM + n] + acc[i][j][h * 2 + e]) + b2[n];
                    g_icb[(size_t)m * DIM + n] = v;
                    g_chi[(size_t)m * DIM + n] = __float2bfloat16(v);
                    ss += v * v;
                }
            }
            ss += __shfl_down_sync(0xffffffffu, ss, 1, 4);
            ss += __shfl_down_sync(0xffffffffu, ss, 2, 4);
            if (t == 0) g_ccpart[part * CSIZE + m] = ss;
        }
    }
}

// ---------------- cc finalize ----------------
__global__ void ccfin_k() {
    int i = blockIdx.x * 256 + threadIdx.x;
    float cc = 0.f;
#pragma unroll
    for (int p = 0; p < 8; p++) cc += g_ccpart[p * CSIZE + i];
    g_cc[i] = cc;
    float mx = cc;
    for (int o = 16; o > 0; o >>= 1) mx = fmaxf(mx, __shfl_down_sync(0xffffffffu, mx, o));
    __shared__ float sb[8];
    int tid = threadIdx.x;
    if ((tid & 31) == 0) sb[tid >> 5] = mx;
    __syncthreads();
    if (tid == 0) {
        float t = sb[0];
#pragma unroll
        for (int k = 1; k < 8; k++) t = fmaxf(t, sb[k]);
        atomicMax(&g_maxcc_u, ord_enc(t));
    }
}

// ---------------- Phase 1: approx bf16 dist GEMM + candidate filter --------
// CTA 128x128, 8 warps 32x64, KC=64, 2 buffers (occ 2), single sync/stage:
// wait0 -> sync -> issue(s+1) -> compute(s).
__global__ void __launch_bounds__(256, 2) dist_mma_k() {
    extern __shared__ char smem[];
    uint32_t sbase = smem_u32(smem);
    float* s_cc = (float*)smem;

    int tid = threadIdx.x;
    int wid = tid >> 5, lane = tid & 31;
    int bn = blockIdx.x * NT;
    int bm = blockIdx.y * MT;

    int wm = (wid & 3) * 32;
    int wn = (wid >> 2) * 64;

    if (tid < NT) s_cc[tid] = g_cc[bn + tid];
    float maxcc = ord_dec(g_maxcc_u);

    float acc[2][8][4];
#pragma unroll
    for (int i = 0; i < 2; i++)
#pragma unroll
        for (int j = 0; j < 8; j++)
#pragma unroll
            for (int r = 0; r < 4; r++) acc[i][j][r] = 0.f;

    auto issue_stage = [&](int s, uint32_t buf) {
        int k0 = s * KC;
#pragma unroll
        for (int r = 0; r < 4; r++) {
            int c = tid + 256 * r;                 // 0..1023
            int row = c >> 3, part = c & 7;
            uint32_t so = (uint32_t)(row * ROWB + part * 16);
            CP_ASYNC16(buf + so, g_xhi + (size_t)(bm + row) * DIM + k0 + part * 8);
            CP_ASYNC16(buf + OFF_B + so, g_chi + (size_t)(bn + row) * DIM + k0 + part * 8);
        }
    };

    uint32_t buf0 = sbase + SM_BUF0;
    issue_stage(0, buf0);
    CP_COMMIT();

    int g = lane >> 3;
    uint32_t arow_l = (uint32_t)((wm + (lane & 15)) * ROWB + (lane >> 4) * 16);
    uint32_t brow_l = (uint32_t)((wn + (g >> 1) * 8 + (lane & 7)) * ROWB + (g & 1) * 16);

    for (int s = 0; s < NSTG; s++) {
        CP_WAIT0();          // stage s has landed
        __syncthreads();     // all warps done reading stage s-1 (other buffer)
        if (s + 1 < NSTG) {
            issue_stage(s + 1, buf0 + (uint32_t)((s + 1) & 1) * SM_STAGE);
            CP_COMMIT();
        }

        uint32_t buf = buf0 + (uint32_t)(s & 1) * SM_STAGE;
#pragma unroll
        for (int kk = 0; kk < 4; kk++) {
            int kb = kk * 32;
            uint32_t ahi0[4], ahi1[4];
            ldm_x4(ahi0, buf + arow_l + kb);
            ldm_x4(ahi1, buf + arow_l + kb + 16 * ROWB);

            uint32_t baddr = buf + OFF_B + brow_l + kb;
#pragma unroll
            for (int jp = 0; jp < 4; jp++) {
                uint32_t bfrag[4];
                ldm_x4(bfrag, baddr + (uint32_t)(jp * 16 * ROWB));
                mma_bf16(acc[0][2 * jp + 0], ahi0, bfrag + 0);
                mma_bf16(acc[0][2 * jp + 1], ahi0, bfrag + 2);
                mma_bf16(acc[1][2 * jp + 0], ahi1, bfrag + 0);
                mma_bf16(acc[1][2 * jp + 1], ahi1, bfrag + 2);
            }
        }
    }

    int q = lane >> 2, t = lane & 3;
#pragma unroll
    for (int i = 0; i < 2; i++) {
#pragma unroll
        for (int h = 0; h < 2; h++) {
            int row = bm + wm + i * 16 + h * 8 + q;
            float xxv = g_xx[row];
            float d2s[16];
            float best = 3.4e38f;
#pragma unroll
            for (int j = 0; j < 8; j++) {
#pragma unroll
                for (int e = 0; e < 2; e++) {
                    float dot = acc[i][j][h * 2 + e];
                    float d2 = __fadd_rn(__fadd_rn(xxv, __fmul_rn(dot, -2.0f)),
                                         s_cc[wn + j * 8 + 2 * t + e]);
                    d2s[j * 2 + e] = d2;
                    best = fminf(best, d2);
                }
            }
            unsigned int fb = ord_enc(best);
            unsigned int o1 = __shfl_xor_sync(0xffffffffu, fb, 1);
            fb = (o1 < fb) ? o1 : fb;
            unsigned int o2 = __shfl_xor_sync(0xffffffffu, fb, 2);
            fb = (o2 < fb) ? o2 : fb;
            unsigned int old = 0xFFFFFFFFu;
            if (t == 0) old = atomicMin(&g_rowmin[row], fb);
            old = __shfl_sync(0xffffffffu, old, lane & ~3);
            unsigned int run = (old < fb) ? old : fb;
            float thr = ord_dec(run) + (2.f * sqrtf(xxv * maxcc) * 0.0078125f + 0.01f);
#pragma unroll
            for (int j = 0; j < 8; j++) {
#pragma unroll
                for (int e = 0; e < 2; e++) {
                    if (d2s[j * 2 + e] < thr) {
                        unsigned int slot = atomicAdd(&g_ccount[row], 1u);
                        if (slot < CAP)
                            g_cand[row * CAP + slot] = bn + wn + j * 8 + 2 * t + e;
                    }
                }
            }
        }
    }
}

// ---------------- Phase 2 + finish: warp-parallel refine, rotation, loss ----
__global__ void refine_finish_k(const float* __restrict__ X, float* __restrict__ out,
                                int M, long long idx_off)
{
    int m = blockIdx.x;
    int tid = threadIdx.x;   // 128
    int wid = tid >> 5, lane = tid & 31;
    unsigned int cnt = g_ccount[m];
    float xxv = g_xx[m];

    __shared__ float sx[DIM];
    __shared__ unsigned long long wbest[4];
    __shared__ int s_idx;
    __shared__ float sb[16];

    float4 xv4 = *(const float4*)(X + (size_t)m * DIM + tid * 4);
    *(float4*)(sx + tid * 4) = xv4;
    __syncthreads();

    bool fullscan = (cnt == 0u) || (cnt > (unsigned)CAP);
    int n_iter = fullscan ? CSIZE : (int)cnt;

    unsigned long long best = ~0ULL;
    const float4* sx4 = (const float4*)sx;
    for (int s = wid; s < n_iter; s += 4) {
        int c = fullscan ? s : g_cand[m * CAP + s];
        const float4* cr = (const float4*)(g_icb + (size_t)c * DIM);
        float p = 0.f;
#pragma unroll
        for (int i = 0; i < 4; i++) {
            float4 cv = cr[lane + 32 * i];
            float4 xs = sx4[lane + 32 * i];
            p += cv.x * xs.x + cv.y * xs.y + cv.z * xs.z + cv.w * xs.w;
        }
        for (int o = 16; o > 0; o >>= 1) p += __shfl_down_sync(0xffffffffu, p, o);
        if (lane == 0) {
            float d2 = __fadd_rn(__fadd_rn(xxv, __fmul_rn(p, -2.0f)), g_cc[c]);
            unsigned long long key =
                ((unsigned long long)ord_enc(d2) << 32) | (unsigned)c;
            if (key < best) best = key;
        }
    }
    if (lane == 0) wbest[wid] = best;
    __syncthreads();
    if (tid == 0) {
        unsigned long long b = wbest[0];
#pragma unroll
        for (int w = 1; w < 4; w++) if (wbest[w] < b) b = wbest[w];
        s_idx = (int)(b & 0xffffffffu);
    }
    __syncthreads();
    int idx = s_idx;

    float4 qv4 = *(const float4*)(g_icb + (size_t)idx * DIM + tid * 4);
    float xv[4] = {xv4.x, xv4.y, xv4.z, xv4.w};
    float qv[4] = {qv4.x, qv4.y, qv4.z, qv4.w};

    float sx2 = 0.f, sq2 = 0.f, sd2 = 0.f;
#pragma unroll
    for (int i = 0; i < 4; i++) {
        sx2 += xv[i] * xv[i];
        sq2 += qv[i] * qv[i];
        float df = xv[i] - qv[i];
        sd2 += df * df;
    }

    {
        float v0 = sx2, v1 = sq2, v2 = sd2;
        for (int o = 16; o > 0; o >>= 1) {
            v0 += __shfl_down_sync(0xffffffffu, v0, o);
            v1 += __shfl_down_sync(0xffffffffu, v1, o);
            v2 += __shfl_down_sync(0xffffffffu, v2, o);
        }
        if (lane == 0) { sb[wid] = v0; sb[4 + wid] = v1; sb[8 + wid] = v2; }
        __syncthreads();
        sx2 = sb[0] + sb[1] + sb[2] + sb[3];
        sq2 = sb[4] + sb[5] + sb[6] + sb[7];
        sd2 = sb[8] + sb[9] + sb[10] + sb[11];
        __syncthreads();
    }

    float ns = sqrtf(sx2), nt = sqrtf(sq2);
    float ins = 1.f / fmaxf(ns, EPSV);
    float inv_t = 1.f / fmaxf(nt, EPSV);

    float wv[4];
    float sw2 = 0.f, sxw = 0.f;
#pragma unroll
    for (int i = 0; i < 4; i++) {
        float w = xv[i] * ins + qv[i] * inv_t;
        wv[i] = w;
        sw2 += w * w;
        sxw += xv[i] * w;
    }
    {
        float v0 = sw2, v1 = sxw;
        for (int o = 16; o > 0; o >>= 1) {
            v0 += __shfl_down_sync(0xffffffffu, v0, o);
            v1 += __shfl_down_sync(0xffffffffu, v1, o);
        }
        if (lane == 0) { sb[wid] = v0; sb[4 + wid] = v1; }
        __syncthreads();
        sw2 = sb[0] + sb[1] + sb[2] + sb[3];
        sxw = sb[4] + sb[5] + sb[6] + sb[7];
        __syncthreads();
    }

    float iwn = 1.f / fmaxf(sqrtf(sw2), EPSV);
    float xdw = sxw * iwn;
    float xdu = sx2 * ins;
    float scl = nt * ins;

    float4 o4;
    float ov[4];
#pragma unroll
    for (int i = 0; i < 4; i++) {
        float r = xv[i] - 2.f * xdw * (wv[i] * iwn) + 2.f * xdu * (qv[i] * inv_t);
        ov[i] = r * scl;
    }
    o4.x = ov[0]; o4.y = ov[1]; o4.z = ov[2]; o4.w = ov[3];
    *(float4*)(out + (size_t)m * DIM + tid * 4) = o4;

    if (tid == 0) {
        g_rowloss[m] = sd2;
        if (idx_off >= 0) out[idx_off + m] = (float)idx;
    }
}

__global__ void loss_k(float* __restrict__ out, int M, long long pos) {
    int tid = threadIdx.x;
    float s = 0.f;
    for (int i = tid; i < M; i += 256) s += g_rowloss[i];
    for (int o = 16; o > 0; o >>= 1) s += __shfl_down_sync(0xffffffffu, s, o);
    __shared__ float sb[8];
    if ((tid & 31) == 0) sb[tid >> 5] = s;
    __syncthreads();
    if (tid == 0) {
        float t = 0.f;
        for (int i = 0; i < 8; i++) t += sb[i];
        if (pos >= 0) out[pos] = 1.25f * t / (float)((size_t)M * DIM);
    }
}

// ---------------- host launcher ----------------
extern "C" void kernel_launch(void* const* d_in, const int* in_sizes, int n_in,
                              void* d_out, int out_size)
{
    const float* x  = (const float*)d_in[0];
    const float* cb = (const float*)d_in[1];
    const float* W1 = (const float*)d_in[2];
    const float* b1 = (const float*)d_in[3];
    const float* W2 = (const float*)d_in[4];
    const float* b2 = (const float*)d_in[5];
    float* out = (float*)d_out;

    int M = in_sizes[0] / DIM;
    long long NQ = (long long)M * DIM;

    long long idx_off = (out_size >= NQ + M) ? NQ : -1;
    long long loss_pos = -1;
    if (out_size >= NQ + M + 1) loss_pos = NQ + M;
    else if (out_size == NQ + 1) loss_pos = NQ;

    __nv_bfloat16 *p_w1thi, *p_w1tlo, *p_w2thi, *p_w2tlo;
    cudaGetSymbolAddress((void**)&p_w1thi, g_w1thi);
    cudaGetSymbolAddress((void**)&p_w1tlo, g_w1tlo);
    cudaGetSymbolAddress((void**)&p_w2thi, g_w2thi);
    cudaGetSymbolAddress((void**)&p_w2tlo, g_w2tlo);

    cudaFuncSetAttribute(dist_mma_k, cudaFuncAttributeMaxDynamicSharedMemorySize, SM_TOTAL);
    cudaFuncSetAttribute(gemm1_mma_k, cudaFuncAttributeMaxDynamicSharedMemorySize, G2_TOTAL);
    cudaFuncSetAttribute(gemm2_mma_k, cudaFuncAttributeMaxDynamicSharedMemorySize, G2_TOTAL);

    cudaMemsetAsync(d_out, 0, (size_t)out_size * sizeof(float));

    prep_x_k<<<M, 128>>>(x);
    cbprep_k<<<CSIZE * CDIM / 1024, 256>>>(cb);
    wtprep_k<<<dim3(DIM / 32, CDIM / 32), dim3(32, 8)>>>(W1, p_w1thi, p_w1tlo, CDIM, DIM);
    wtprep_k<<<dim3(DIM / 32, DIM / 32), dim3(32, 8)>>>(W2, p_w2thi, p_w2tlo, DIM, DIM);

    gemm1_mma_k<<<dim3(DIM / 128, CSIZE / 128), 256, G2_TOTAL>>>(b1);
    gemm2_mma_k<<<dim3(DIM / 128, CSIZE / 128), 256, G2_TOTAL>>>(b2);
    ccfin_k<<<CSIZE / 256, 256>>>();

    dist_mma_k<<<dim3(CSIZE / NT, M / MT), 256, SM_TOTAL>>>();

    refine_finish_k<<<M, 128>>>(x, out, M, idx_off);
    loss_k<<<1, 256>>>(out, M, loss_pos);
}